// round 16
// baseline (speedup 1.0000x reference)
#include <cuda_runtime.h>
#include <cuda_fp16.h>
#include <cstdint>
#include <math.h>

#define T_SEQ 2048
#define DMODEL 2048
#define NH 32
#define NKV 8
#define HD 64

// Q pre-scale: 1/sqrt(64) * log2(e)  (softmax runs in exp2 domain)
#define QSCALE 0.1803368801111364f

// ---------------- Scratch (device globals; allocation-free) ----------------
// fp16 operand globals use the k16 permutation: within each 16-half k-block,
// logical k = b*8 + 2*tig + lo stored at slot tig*4 + b*2 + lo. Applied
// identically to both MMA operands' k dim -> dot products preserved.
__device__ __half g_qh [(size_t)2 * NH * T_SEQ * HD];   // fp16 Q*QSCALE (b,h,t,d) natural
__device__ __half g_ctx[(size_t)2 * T_SEQ * NH * HD];   // fp16 ctx PERM16
__device__ __half g_xt [(size_t)4096 * 2048];           // fp16 x PERM16
__device__ __half g_wq [(size_t)2048 * 2048];           // PERM16
__device__ __half g_wk [(size_t)512 * 2048];            // PERM16
__device__ __half g_wv [(size_t)512 * 2048];            // PERM16
__device__ __half g_wo [(size_t)2048 * 2048];           // PERM16
__device__ __half g_kc [(size_t)2 * NKV * T_SEQ * HD];  // fp16 K PERM16(d)
__device__ __half g_vt [(size_t)2 * NKV * HD * T_SEQ];  // fp16 V^T PERM16(t)

__device__ __forceinline__ uint32_t pack_h2(float a, float b) {
    __half2 h = __floats2half2_rn(a, b);
    return *(uint32_t*)&h;
}

__device__ __forceinline__ float fast_exp2(float x) {
    float y;
    asm("ex2.approx.f32 %0, %1;" : "=f"(y) : "f"(x));
    return y;
}

__device__ __forceinline__ void mma_f16(float* c, uint32_t a0, uint32_t a1,
                                        uint32_t a2, uint32_t a3,
                                        uint32_t b0, uint32_t b1) {
    asm volatile(
        "mma.sync.aligned.m16n8k16.row.col.f32.f16.f16.f32 "
        "{%0,%1,%2,%3}, {%4,%5,%6,%7}, {%8,%9}, {%0,%1,%2,%3};"
        : "+f"(c[0]), "+f"(c[1]), "+f"(c[2]), "+f"(c[3])
        : "r"(a0), "r"(a1), "r"(a2), "r"(a3), "r"(b0), "r"(b1));
}

__device__ __forceinline__ uint32_t smem_u32(const void* p) {
    uint32_t a;
    asm("{ .reg .u64 t; cvta.to.shared.u64 t, %1; cvt.u32.u64 %0, t; }"
        : "=r"(a) : "l"(p));
    return a;
}
#define CP_ASYNC16_CG(dst, src) \
    asm volatile("cp.async.cg.shared.global [%0], [%1], 16;" :: "r"(dst), "l"(src))
#define CP_ASYNC16_CA(dst, src) \
    asm volatile("cp.async.ca.shared.global [%0], [%1], 16;" :: "r"(dst), "l"(src))
#define CP_COMMIT() asm volatile("cp.async.commit_group;" ::: "memory")
#define CP_WAIT0()  asm volatile("cp.async.wait_group 0;" ::: "memory")
#define CP_WAIT2()  asm volatile("cp.async.wait_group 2;" ::: "memory")

// ============================================================================
// Prep: all fp32 -> fp16 PERM16, one launch.
// ============================================================================
__global__ void cvt_all(const float* __restrict__ x,
                        const float* __restrict__ wq,
                        const float* __restrict__ wk,
                        const float* __restrict__ wv,
                        const float* __restrict__ wo,
                        __half* __restrict__ xt,
                        __half* __restrict__ wqt,
                        __half* __restrict__ wkt,
                        __half* __restrict__ wvt,
                        __half* __restrict__ wot)
{
    int i = blockIdx.x * blockDim.x + threadIdx.x;
    const float* in;
    __half* out;
    if (i < 2097152)        { in = x;  out = xt; }
    else if (i < 3145728)   { in = wq; out = wqt; i -= 2097152; }
    else if (i < 3407872)   { in = wk; out = wkt; i -= 3145728; }
    else if (i < 3670016)   { in = wv; out = wvt; i -= 3407872; }
    else                    { in = wo; out = wot; i -= 3670016; }
    float4 v = ((const float4*)in)[i];
    const int w0 = i * 4;
    const int blockbase = w0 & ~15;
    const int k0 = w0 & 15;
    const int u = (k0 >> 2) & 1;
    const int b = (k0 >> 3) & 1;
    const int s0 = 8 * u + 2 * b;
    *(__half2*)&out[blockbase + s0]     = __floats2half2_rn(v.x, v.y);
    *(__half2*)&out[blockbase + s0 + 4] = __floats2half2_rn(v.z, v.w);
}

// ============================================================================
// 4-stage cp.async.cg fp16 GEMM: 128x128 tile, BK=32 halves, 8 warps (2x4),
// warp tile 64x32, m16n8k16. PERM16 operands, pitch 48 halves (96B):
// bank map (12*gr+tig) mod 16 is a permutation -> conflict-free LDS.64.
// Pipeline: fills for s+3 issued at iter s; wait_group 2 (empty commits at
// tail keep group count aligned) -> 3 stage-times of fill latency slack.
// KIND 0: fused QKV. bx<16: Q+RoPE -> g_qh fp16*QSCALE (natural);
//         16..19: K+RoPE -> kout fp32 + g_kc fp16 PERM16;
//         20..23: V -> vout fp32 + g_vt fp16 V^T PERM16 (vtrans fused).
// KIND 1: O projection: A=g_ctx (fp16 PERM16), C=out fp32.
// ============================================================================
#define GP2 48
#define ST_H (128 * GP2)   // 6144 halves per operand per stage

template <int KIND>
__global__ __launch_bounds__(256, 2) void db_gemm(
    const __half* __restrict__ xA,
    const float* __restrict__ bq, const float* __restrict__ bk,
    const float* __restrict__ bv,
    float* __restrict__ kout, float* __restrict__ vout,
    float* __restrict__ outC,
    const float* __restrict__ cosT, const float* __restrict__ sinT)
{
    extern __shared__ __align__(16) __half smh[];
    const uint32_t sm_addr = smem_u32(smh);

    const int tid = threadIdx.x;
    const int wid = tid >> 5;
    const int lane = tid & 31;
    const int gr = lane >> 2;
    const int tig = lane & 3;
    const int wm = wid >> 2;
    const int wn = wid & 3;

    constexpr int K = DMODEL;
    const int m0 = blockIdx.y * 128;

    int mode, n0;
    const __half* A;
    const __half* W;
    const float* bias;
    if (KIND == 1) {
        mode = 0; n0 = blockIdx.x * 128; A = g_ctx; W = g_wo; bias = bq;
    } else {
        const int bx = blockIdx.x;
        A = xA;
        if (bx < 16)      { mode = 1; n0 = bx * 128;        W = g_wq; bias = bq; }
        else if (bx < 20) { mode = 2; n0 = (bx - 16) * 128; W = g_wk; bias = bk; }
        else              { mode = 3; n0 = (bx - 20) * 128; W = g_wv; bias = bv; }
    }

    // fills: 2 chunks per op per thread: row = tid>>1, cols (tid&1)*16 + {0,8}
    const int frow = tid >> 1;
    const int fcb = (tid & 1) * 16;
    const __half* Asrc = A + (size_t)(m0 + frow) * K + fcb;
    const __half* Wsrc = W + (size_t)(n0 + frow) * K + fcb;
    const uint32_t dstb = (uint32_t)(frow * GP2 + fcb) * 2;

    float acc[4][4][4];
#pragma unroll
    for (int mi = 0; mi < 4; mi++)
#pragma unroll
        for (int ni = 0; ni < 4; ni++)
#pragma unroll
            for (int r = 0; r < 4; r++) acc[mi][ni][r] = 0.f;

    const int NST = K / 32;   // 64 stages

    // Prologue: fill stages 0,1,2 (one commit group each)
#pragma unroll
    for (int s = 0; s < 3; s++) {
        const uint32_t boff = (uint32_t)s * (2 * ST_H * 2);
        const int ko = s * 32;
        CP_ASYNC16_CG(sm_addr + boff + dstb, Asrc + ko);
        CP_ASYNC16_CG(sm_addr + boff + dstb + 16, Asrc + ko + 8);
        CP_ASYNC16_CG(sm_addr + boff + ST_H * 2 + dstb, Wsrc + ko);
        CP_ASYNC16_CG(sm_addr + boff + ST_H * 2 + dstb + 16, Wsrc + ko + 8);
        CP_COMMIT();
    }

    for (int s = 0; s < NST; s++) {
        CP_WAIT2();
        __syncthreads();
        if (s + 3 < NST) {
            const uint32_t boff = (uint32_t)((s + 3) & 3) * (2 * ST_H * 2);
            const int ko = (s + 3) * 32;
            CP_ASYNC16_CG(sm_addr + boff + dstb, Asrc + ko);
            CP_ASYNC16_CG(sm_addr + boff + dstb + 16, Asrc + ko + 8);
            CP_ASYNC16_CG(sm_addr + boff + ST_H * 2 + dstb, Wsrc + ko);
            CP_ASYNC16_CG(sm_addr + boff + ST_H * 2 + dstb + 16, Wsrc + ko + 8);
        }
        CP_COMMIT();   // unconditional: keeps wait_group arithmetic valid at tail

        const __half* Abase = smh + (s & 3) * 2 * ST_H + (wm * 64) * GP2;
        const __half* Bbase = smh + (s & 3) * 2 * ST_H + ST_H + (wn * 32) * GP2;
#pragma unroll
        for (int blk = 0; blk < 2; blk++) {
            const int kc = blk * 16 + tig * 4;
            uint32_t bf[4][2];
#pragma unroll
            for (int ni = 0; ni < 4; ni++) {
                uint64_t bv = *(const uint64_t*)&Bbase[(ni * 8 + gr) * GP2 + kc];
                bf[ni][0] = (uint32_t)bv;
                bf[ni][1] = (uint32_t)(bv >> 32);
            }
#pragma unroll
            for (int mi = 0; mi < 4; mi++) {
                uint64_t aL = *(const uint64_t*)&Abase[(mi * 16 + gr) * GP2 + kc];
                uint64_t aH = *(const uint64_t*)&Abase[(mi * 16 + gr + 8) * GP2 + kc];
                const uint32_t a0 = (uint32_t)aL, a2 = (uint32_t)(aL >> 32);
                const uint32_t a1 = (uint32_t)aH, a3 = (uint32_t)(aH >> 32);
#pragma unroll
                for (int ni = 0; ni < 4; ni++)
                    mma_f16(acc[mi][ni], a0, a1, a2, a3, bf[ni][0], bf[ni][1]);
            }
        }
    }

    // ---------------- Register epilogue ----------------
#pragma unroll
    for (int mi = 0; mi < 4; mi++) {
#pragma unroll
        for (int half = 0; half < 2; half++) {
            const int m = m0 + wm * 64 + mi * 16 + gr + half * 8;
            const int bb = m >> 11;
            const int t = m & (T_SEQ - 1);
#pragma unroll
            for (int ni = 0; ni < 4; ni++) {
                const int n = n0 + wn * 32 + ni * 8 + tig * 2;
                float v0 = acc[mi][ni][half * 2 + 0] + bias[n];
                float v1 = acc[mi][ni][half * 2 + 1] + bias[n + 1];
                if (mode == 1 || mode == 2) {
                    const int hh = (n & 63) >> 1;
                    const float c = cosT[t * (HD / 2) + hh];
                    const float ss = sinT[t * (HD / 2) + hh];
                    const float e = v0 * c - v1 * ss;
                    const float o = v0 * ss + v1 * c;
                    v0 = e;
                    v1 = o;
                }
                if (mode == 0) {
                    *(float2*)&outC[(size_t)m * DMODEL + n] = make_float2(v0, v1);
                } else if (mode == 1) {
                    *(__half2*)&g_qh[(((size_t)(bb * NH + (n >> 6))) * T_SEQ + t) * HD + (n & 63)] =
                        __floats2half2_rn(v0 * QSCALE, v1 * QSCALE);
                } else {
                    const int head = n >> 6;
                    const int d = n & 63;
                    const size_t idx =
                        (((size_t)(bb * NKV + head)) * T_SEQ + t) * HD + d;
                    if (mode == 2) {
                        *(float2*)&kout[idx] = make_float2(v0, v1);
                        const int slot = ((d & 7) >> 1) * 4 + ((d >> 3) & 1) * 2;
                        const size_t base =
                            (((size_t)(bb * NKV + head)) * T_SEQ + t) * HD +
                            (d & ~15) + slot;
                        *(__half2*)&g_kc[base] = __floats2half2_rn(v0, v1);
                    } else {
                        *(float2*)&vout[idx] = make_float2(v0, v1);
                        // fused vtrans: V^T (b,kv,d,t), t PERM16, scalar fp16 stores
                        const int tslot = (t & ~15) +
                                          ((t & 7) >> 1) * 4 + ((t >> 3) & 1) * 2 + (t & 1);
                        __half* vtb = g_vt + (size_t)(bb * NKV + head) * HD * T_SEQ + tslot;
                        vtb[(size_t)d * T_SEQ] = __float2half_rn(v0);
                        vtb[(size_t)(d + 1) * T_SEQ] = __float2half_rn(v1);
                    }
                }
            }
        }
    }
}

// ============================================================================
// Flash attention, fp16 m16n8k16: 8 warps, warp tile 16x64, PERM16 K/V ->
// LDS.64 B-frags (pitch 80 halves), cp.async.ca double-buffered, heavy-first.
// exp2-domain softmax; row-sum l accumulated by ones-column MMA (B-fragment
// of a ones n-column is the register constant gr==0 ? 1h,1h : 0).
// ============================================================================
#define ATP 80
#define KVH (64 * ATP)

__global__ __launch_bounds__(256, 2) void attn_mma()
{
    extern __shared__ __align__(16) __half smh[];
    const uint32_t sm_addr = smem_u32(smh);

    const int tid = threadIdx.x;
    const int wid = tid >> 5;
    const int lane = tid & 31;
    const int gr = lane >> 2;
    const int tig = lane & 3;

    const int qt = (gridDim.x - 1) - blockIdx.x;  // heavy-first
    const int bh = blockIdx.y;
    const int b = bh >> 5;
    const int h = bh & 31;
    const int bkv = (b * NKV) + (h >> 2);

    const __half* Qg = g_qh + (((size_t)(b * NH + h)) * T_SEQ + qt * 128 + wid * 16) * HD;
    uint32_t qa[4][4];
#pragma unroll
    for (int j = 0; j < 4; j++) {
        const int d0 = 16 * j + 2 * tig;
        qa[j][0] = *(const uint32_t*)&Qg[gr * HD + d0];
        qa[j][1] = *(const uint32_t*)&Qg[(gr + 8) * HD + d0];
        qa[j][2] = *(const uint32_t*)&Qg[gr * HD + d0 + 8];
        qa[j][3] = *(const uint32_t*)&Qg[(gr + 8) * HD + d0 + 8];
    }

    const __half* Kbase = g_kc + (size_t)bkv * T_SEQ * HD;
    const __half* Vbase = g_vt + (size_t)bkv * HD * T_SEQ;

    float ctx[8][4];
#pragma unroll
    for (int ni = 0; ni < 8; ni++)
#pragma unroll
        for (int r = 0; r < 4; r++) ctx[ni][r] = 0.f;
    float lac[4] = {0.f, 0.f, 0.f, 0.f};          // l via ones-column MMA
    const uint32_t bones = (gr == 0) ? 0x3C003C00u : 0u;
    float mrun0 = -INFINITY, mrun1 = -INFINITY;

    const int lrow0 = tid >> 3;
    const int lch = tid & 7;
    const int row0 = qt * 128 + wid * 16 + gr;
    const int row1 = row0 + 8;
    const int njt = 2 * qt + 2;

#pragma unroll
    for (int i = 0; i < 2; i++) {
        const int r = lrow0 + i * 32;
        CP_ASYNC16_CA(sm_addr + (r * ATP + lch * 8) * 2, Kbase + (size_t)r * HD + lch * 8);
        CP_ASYNC16_CA(sm_addr + (2 * KVH + r * ATP + lch * 8) * 2,
                      Vbase + (size_t)r * T_SEQ + lch * 8);
    }
    CP_COMMIT();

    for (int jt = 0; jt < njt; jt++) {
        CP_WAIT0();
        __syncthreads();
        if (jt + 1 < njt) {
            const uint32_t boff = (uint32_t)((jt + 1) & 1) * KVH * 2;
            const int kt = (jt + 1) * 64;
#pragma unroll
            for (int i = 0; i < 2; i++) {
                const int r = lrow0 + i * 32;
                CP_ASYNC16_CA(sm_addr + boff + (r * ATP + lch * 8) * 2,
                              Kbase + (size_t)(kt + r) * HD + lch * 8);
                CP_ASYNC16_CA(sm_addr + 2 * KVH * 2 + boff + (r * ATP + lch * 8) * 2,
                              Vbase + (size_t)r * T_SEQ + kt + lch * 8);
            }
            CP_COMMIT();
        }

        if (jt == 2 * qt + 1 && wid < 4) continue;  // fully masked

        const __half* Ks = smh + (jt & 1) * KVH;
        const __half* Vt = smh + 2 * KVH + (jt & 1) * KVH;

        // ---- S (exp2 domain) = (Q*QSCALE) K^T ----
        float s[8][4];
#pragma unroll
        for (int ni = 0; ni < 8; ni++)
#pragma unroll
            for (int r = 0; r < 4; r++) s[ni][r] = 0.f;
#pragma unroll
        for (int j = 0; j < 4; j++) {
            const int kc = j * 16 + tig * 4;
#pragma unroll
            for (int ni = 0; ni < 8; ni++) {
                uint64_t bv = *(const uint64_t*)&Ks[(ni * 8 + gr) * ATP + kc];
                mma_f16(s[ni], qa[j][0], qa[j][1], qa[j][2], qa[j][3],
                        (uint32_t)bv, (uint32_t)(bv >> 32));
            }
        }

        // ---- causal mask ----
        if (jt >= 2 * qt) {
            const int colb = jt * 64 + 2 * tig;
#pragma unroll
            for (int ni = 0; ni < 8; ni++) {
                const int c0 = colb + 8 * ni;
                if (c0 > row0) s[ni][0] = -INFINITY;
                if (c0 + 1 > row0) s[ni][1] = -INFINITY;
                if (c0 > row1) s[ni][2] = -INFINITY;
                if (c0 + 1 > row1) s[ni][3] = -INFINITY;
            }
        }

        // ---- online softmax (exp2 domain; l handled by ones-MMA) ----
        float m0 = -INFINITY, m1 = -INFINITY;
#pragma unroll
        for (int ni = 0; ni < 8; ni++) {
            m0 = fmaxf(m0, fmaxf(s[ni][0], s[ni][1]));
            m1 = fmaxf(m1, fmaxf(s[ni][2], s[ni][3]));
        }
        m0 = fmaxf(m0, __shfl_xor_sync(0xffffffffu, m0, 1, 4));
        m0 = fmaxf(m0, __shfl_xor_sync(0xffffffffu, m0, 2, 4));
        m1 = fmaxf(m1, __shfl_xor_sync(0xffffffffu, m1, 1, 4));
        m1 = fmaxf(m1, __shfl_xor_sync(0xffffffffu, m1, 2, 4));
        const float mn0 = fmaxf(mrun0, m0);
        const float mn1 = fmaxf(mrun1, m1);
        const float al0 = fast_exp2(mrun0 - mn0);
        const float al1 = fast_exp2(mrun1 - mn1);
#pragma unroll
        for (int ni = 0; ni < 8; ni++) {
            s[ni][0] = fast_exp2(s[ni][0] - mn0);
            s[ni][1] = fast_exp2(s[ni][1] - mn0);
            s[ni][2] = fast_exp2(s[ni][2] - mn1);
            s[ni][3] = fast_exp2(s[ni][3] - mn1);
            ctx[ni][0] *= al0;
            ctx[ni][1] *= al0;
            ctx[ni][2] *= al1;
            ctx[ni][3] *= al1;
        }
        lac[0] *= al0;
        lac[1] *= al0;
        lac[2] *= al1;
        lac[3] *= al1;
        mrun0 = mn0;
        mrun1 = mn1;

        // ---- ctx += P V (+ l += P * ones) ----
#pragma unroll
        for (int j = 0; j < 4; j++) {
            const uint32_t a0 = pack_h2(s[2 * j][0], s[2 * j][1]);
            const uint32_t a1 = pack_h2(s[2 * j][2], s[2 * j][3]);
            const uint32_t a2 = pack_h2(s[2 * j + 1][0], s[2 * j + 1][1]);
            const uint32_t a3 = pack_h2(s[2 * j + 1][2], s[2 * j + 1][3]);
            const int kc = j * 16 + tig * 4;
#pragma unroll
            for (int ni = 0; ni < 8; ni++) {
                uint64_t bv = *(const uint64_t*)&Vt[(ni * 8 + gr) * ATP + kc];
                mma_f16(ctx[ni], a0, a1, a2, a3, (uint32_t)bv, (uint32_t)(bv >> 32));
            }
            mma_f16(lac, a0, a1, a2, a3, bones, bones);
        }
    }

    // ---- finalize: l lives in col 0 (tig==0's c0/c2); broadcast within quad ----
    const float l0 = __shfl_sync(0xffffffffu, lac[0], 0, 4);
    const float l1 = __shfl_sync(0xffffffffu, lac[2], 0, 4);
    const float inv0 = 1.0f / l0;
    const float inv1 = 1.0f / l1;
    __half* o0 = g_ctx + (((size_t)(b * T_SEQ + row0)) * NH + h) * HD;
    __half* o1 = g_ctx + (((size_t)(b * T_SEQ + row1)) * NH + h) * HD;
#pragma unroll
    for (int ni = 0; ni < 8; ni++) {
        const int d = ni * 8 + 2 * tig;
        const int word = (d & ~15) + tig * 4 + (ni & 1) * 2;  // PERM slot
        *(__half2*)&o0[word] = __floats2half2_rn(ctx[ni][0] * inv0, ctx[ni][1] * inv0);
        *(__half2*)&o1[word] = __floats2half2_rn(ctx[ni][2] * inv1, ctx[ni][3] * inv1);
    }
}

// ---------------------------------------------------------------------------
extern "C" void kernel_launch(void* const* d_in, const int* in_sizes, int n_in,
                              void* d_out, int out_size)
{
    const float* x    = (const float*)d_in[0];
    const float* cosT = (const float*)d_in[1];
    const float* sinT = (const float*)d_in[2];
    const float* wq   = (const float*)d_in[3];
    const float* bq   = (const float*)d_in[4];
    const float* wk   = (const float*)d_in[5];
    const float* bk   = (const float*)d_in[6];
    const float* wv   = (const float*)d_in[7];
    const float* bv   = (const float*)d_in[8];
    const float* wo   = (const float*)d_in[9];
    const float* bo   = (const float*)d_in[10];

    float* out  = (float*)d_out;            // (B, T, D)
    float* kout = out + (size_t)8388608;    // (B, KV, T, HD)
    float* vout = out + (size_t)10485760;   // (B, KV, T, HD)

    const int GEMM_SMEM = 4 * 2 * ST_H * 2;  // 98304 B (4 stages x A+B)
    const int ATTN_SMEM = 4 * KVH * 2;       // 40960 B
    static bool attr_set = false;
    if (!attr_set) {
        cudaFuncSetAttribute(db_gemm<0>, cudaFuncAttributeMaxDynamicSharedMemorySize, GEMM_SMEM);
        cudaFuncSetAttribute(db_gemm<1>, cudaFuncAttributeMaxDynamicSharedMemorySize, GEMM_SMEM);
        cudaFuncSetAttribute(attn_mma, cudaFuncAttributeMaxDynamicSharedMemorySize, ATTN_SMEM);
        attr_set = true;
    }

    __half* p_xt;  cudaGetSymbolAddress((void**)&p_xt, g_xt);
    __half* p_wq;  cudaGetSymbolAddress((void**)&p_wq, g_wq);
    __half* p_wk;  cudaGetSymbolAddress((void**)&p_wk, g_wk);
    __half* p_wv;  cudaGetSymbolAddress((void**)&p_wv, g_wv);
    __half* p_wo;  cudaGetSymbolAddress((void**)&p_wo, g_wo);

    // Prep: fp32 -> fp16 PERM16, one launch
    cvt_all<<<18432, 256>>>(x, wq, wk, wv, wo, p_xt, p_wq, p_wk, p_wv, p_wo);

    // Fused QKV projections (+RoPE; Q -> fp16*QSCALE; K -> fp32 + fp16 PERM16;
    // V -> fp32 + fp16 V^T PERM16, vtrans fused)
    db_gemm<0><<<dim3(24, 32), 256, GEMM_SMEM>>>(
        p_xt, bq, bk, bv, kout, vout, nullptr, cosT, sinT);

    // Attention -> g_ctx (PERM16 fp16)
    attn_mma<<<dim3(T_SEQ / 128, 2 * NH), 256, ATTN_SMEM>>>();

    // Output projection -> out
    db_gemm<1><<<dim3(16, 32), 256, GEMM_SMEM>>>(
        nullptr, bo, nullptr, nullptr, nullptr, nullptr, out, nullptr, nullptr);
}

// round 17
// speedup vs baseline: 1.2088x; 1.2088x over previous
#include <cuda_runtime.h>
#include <cuda_fp16.h>
#include <cstdint>
#include <math.h>

#define T_SEQ 2048
#define DMODEL 2048
#define NH 32
#define NKV 8
#define HD 64

// Q pre-scale: 1/sqrt(64) * log2(e)  (softmax runs in exp2 domain)
#define QSCALE 0.1803368801111364f

// ---------------- Scratch (device globals; allocation-free) ----------------
// fp16 operand globals use the k16 permutation: within each 16-half k-block,
// logical k = b*8 + 2*tig + lo stored at slot tig*4 + b*2 + lo. Applied
// identically to both MMA operands' k dim -> dot products preserved.
__device__ __half g_qh [(size_t)2 * NH * T_SEQ * HD];   // fp16 Q*QSCALE (b,h,t,d) natural
__device__ __half g_ctx[(size_t)2 * T_SEQ * NH * HD];   // fp16 ctx PERM16
__device__ __half g_xt [(size_t)4096 * 2048];           // fp16 x PERM16
__device__ __half g_wq [(size_t)2048 * 2048];           // PERM16
__device__ __half g_wk [(size_t)512 * 2048];            // PERM16
__device__ __half g_wv [(size_t)512 * 2048];            // PERM16
__device__ __half g_wo [(size_t)2048 * 2048];           // PERM16
__device__ __half g_kc [(size_t)2 * NKV * T_SEQ * HD];  // fp16 K PERM16(d)
__device__ __half g_vt [(size_t)2 * NKV * HD * T_SEQ];  // fp16 V^T PERM16(t)

__device__ __forceinline__ uint32_t pack_h2(float a, float b) {
    __half2 h = __floats2half2_rn(a, b);
    return *(uint32_t*)&h;
}

__device__ __forceinline__ float fast_exp2(float x) {
    float y;
    asm("ex2.approx.f32 %0, %1;" : "=f"(y) : "f"(x));
    return y;
}

__device__ __forceinline__ void mma_f16(float* c, uint32_t a0, uint32_t a1,
                                        uint32_t a2, uint32_t a3,
                                        uint32_t b0, uint32_t b1) {
    asm volatile(
        "mma.sync.aligned.m16n8k16.row.col.f32.f16.f16.f32 "
        "{%0,%1,%2,%3}, {%4,%5,%6,%7}, {%8,%9}, {%0,%1,%2,%3};"
        : "+f"(c[0]), "+f"(c[1]), "+f"(c[2]), "+f"(c[3])
        : "r"(a0), "r"(a1), "r"(a2), "r"(a3), "r"(b0), "r"(b1));
}

__device__ __forceinline__ uint32_t smem_u32(const void* p) {
    uint32_t a;
    asm("{ .reg .u64 t; cvta.to.shared.u64 t, %1; cvt.u32.u64 %0, t; }"
        : "=r"(a) : "l"(p));
    return a;
}
#define CP_ASYNC16_CG(dst, src) \
    asm volatile("cp.async.cg.shared.global [%0], [%1], 16;" :: "r"(dst), "l"(src))
#define CP_ASYNC16_CA(dst, src) \
    asm volatile("cp.async.ca.shared.global [%0], [%1], 16;" :: "r"(dst), "l"(src))
#define CP_COMMIT() asm volatile("cp.async.commit_group;" ::: "memory")
#define CP_WAIT0()  asm volatile("cp.async.wait_group 0;" ::: "memory")

// ============================================================================
// Prep: all fp32 -> fp16 PERM16, one launch. (exact R15)
// ============================================================================
__global__ void cvt_all(const float* __restrict__ x,
                        const float* __restrict__ wq,
                        const float* __restrict__ wk,
                        const float* __restrict__ wv,
                        const float* __restrict__ wo,
                        __half* __restrict__ xt,
                        __half* __restrict__ wqt,
                        __half* __restrict__ wkt,
                        __half* __restrict__ wvt,
                        __half* __restrict__ wot)
{
    int i = blockIdx.x * blockDim.x + threadIdx.x;
    const float* in;
    __half* out;
    if (i < 2097152)        { in = x;  out = xt; }
    else if (i < 3145728)   { in = wq; out = wqt; i -= 2097152; }
    else if (i < 3407872)   { in = wk; out = wkt; i -= 3145728; }
    else if (i < 3670016)   { in = wv; out = wvt; i -= 3407872; }
    else                    { in = wo; out = wot; i -= 3670016; }
    float4 v = ((const float4*)in)[i];
    const int w0 = i * 4;
    const int blockbase = w0 & ~15;
    const int k0 = w0 & 15;
    const int u = (k0 >> 2) & 1;
    const int b = (k0 >> 3) & 1;
    const int s0 = 8 * u + 2 * b;
    *(__half2*)&out[blockbase + s0]     = __floats2half2_rn(v.x, v.y);
    *(__half2*)&out[blockbase + s0 + 4] = __floats2half2_rn(v.z, v.w);
}

// ============================================================================
// Prep: V (b,kv,t,d) fp32 -> V^T (b,kv,d,t) fp16, key dim PERM16. (exact R15)
// ============================================================================
__global__ void vtrans(const float* __restrict__ vin, __half* __restrict__ vt)
{
    __shared__ float ts[64 * 65];
    const int tid = threadIdx.x;
    const int jt = blockIdx.x;
    const int bkv = blockIdx.y;

    const float* in = vin + ((size_t)bkv * T_SEQ + jt * 64) * HD;
#pragma unroll
    for (int p = 0; p < 4; p++) {
        const int lin = p * 256 + tid;
        const int t = lin >> 4;
        const int dq = (lin & 15) * 4;
        float4 v = *(const float4*)&in[t * HD + dq];
        ts[(dq + 0) * 65 + t] = v.x;
        ts[(dq + 1) * 65 + t] = v.y;
        ts[(dq + 2) * 65 + t] = v.z;
        ts[(dq + 3) * 65 + t] = v.w;
    }
    __syncthreads();
    __half* out = vt + (size_t)bkv * HD * T_SEQ + jt * 64;
#pragma unroll
    for (int p = 0; p < 4; p++) {
        const int lin = p * 256 + tid;
        const int d = lin >> 4;
        const int cq = (lin & 15) * 4;
        const int blockbase = cq & ~15;
        const int k0 = cq & 15;
        const int u = (k0 >> 2) & 1;
        const int b = (k0 >> 3) & 1;
        const int s0 = 8 * u + 2 * b;
        *(__half2*)&out[(size_t)d * T_SEQ + blockbase + s0] =
            __floats2half2_rn(ts[d * 65 + cq + 0], ts[d * 65 + cq + 1]);
        *(__half2*)&out[(size_t)d * T_SEQ + blockbase + s0 + 4] =
            __floats2half2_rn(ts[d * 65 + cq + 2], ts[d * 65 + cq + 3]);
    }
}

// ============================================================================
// cp.async.cg double-buffered fp16 GEMM (exact R15 config): 128x128 tile,
// BK=64, 8 warps (2x4), warp tile 64x32, m16n8k16, PERM16, pitch 80 halves.
// KIND 0: fused QKV. bx<16: Q+RoPE -> g_qh fp16*QSCALE (natural);
//         16..19: K+RoPE -> kout fp32 + g_kc fp16 PERM16; 20..23: V -> vout.
// KIND 1: O projection: A=g_ctx (fp16 PERM16), C=out fp32.
// ============================================================================
#define GP 80
#define TILE_H (128 * GP)

template <int KIND>
__global__ __launch_bounds__(256, 2) void db_gemm(
    const __half* __restrict__ xA,
    const float* __restrict__ bq, const float* __restrict__ bk,
    const float* __restrict__ bv,
    float* __restrict__ kout, float* __restrict__ vout,
    float* __restrict__ outC,
    const float* __restrict__ cosT, const float* __restrict__ sinT)
{
    extern __shared__ __align__(16) __half smh[];
    const uint32_t sm_addr = smem_u32(smh);

    const int tid = threadIdx.x;
    const int wid = tid >> 5;
    const int lane = tid & 31;
    const int gr = lane >> 2;
    const int tig = lane & 3;
    const int wm = wid >> 2;
    const int wn = wid & 3;

    constexpr int K = DMODEL;
    const int m0 = blockIdx.y * 128;

    int mode, n0;
    const __half* A;
    const __half* W;
    const float* bias;
    if (KIND == 1) {
        mode = 0; n0 = blockIdx.x * 128; A = g_ctx; W = g_wo; bias = bq;
    } else {
        const int bx = blockIdx.x;
        A = xA;
        if (bx < 16)      { mode = 1; n0 = bx * 128;        W = g_wq; bias = bq; }
        else if (bx < 20) { mode = 2; n0 = (bx - 16) * 128; W = g_wk; bias = bk; }
        else              { mode = 3; n0 = (bx - 20) * 128; W = g_wv; bias = bv; }
    }

    const int rbase = tid >> 3;
    const int ch = tid & 7;
    const __half* Asrc = A + (size_t)(m0 + rbase) * K + ch * 8;
    const __half* Wsrc = W + (size_t)(n0 + rbase) * K + ch * 8;
    const uint32_t dstb = (uint32_t)(rbase * GP + ch * 8) * 2;

    float acc[4][4][4];
#pragma unroll
    for (int mi = 0; mi < 4; mi++)
#pragma unroll
        for (int ni = 0; ni < 4; ni++)
#pragma unroll
            for (int r = 0; r < 4; r++) acc[mi][ni][r] = 0.f;

    const int NST = K / 64;
#pragma unroll
    for (int i = 0; i < 4; i++) {
        CP_ASYNC16_CG(sm_addr + i * 32 * GP * 2 + dstb, Asrc + (size_t)i * 32 * K);
        CP_ASYNC16_CG(sm_addr + TILE_H * 2 + i * 32 * GP * 2 + dstb,
                      Wsrc + (size_t)i * 32 * K);
    }
    CP_COMMIT();

    for (int s = 0; s < NST; s++) {
        CP_WAIT0();
        __syncthreads();
        if (s + 1 < NST) {
            const uint32_t boff = (uint32_t)((s + 1) & 1) * (2 * TILE_H * 2);
            const int ko = (s + 1) * 64;
#pragma unroll
            for (int i = 0; i < 4; i++) {
                CP_ASYNC16_CG(sm_addr + boff + i * 32 * GP * 2 + dstb,
                              Asrc + (size_t)i * 32 * K + ko);
                CP_ASYNC16_CG(sm_addr + boff + TILE_H * 2 + i * 32 * GP * 2 + dstb,
                              Wsrc + (size_t)i * 32 * K + ko);
            }
            CP_COMMIT();
        }

        const __half* Abase = smh + (s & 1) * 2 * TILE_H + (wm * 64) * GP;
        const __half* Bbase = smh + (s & 1) * 2 * TILE_H + TILE_H + (wn * 32) * GP;
#pragma unroll
        for (int blk = 0; blk < 4; blk++) {
            const int kc = blk * 16 + tig * 4;
            uint32_t bf[4][2];
#pragma unroll
            for (int ni = 0; ni < 4; ni++) {
                uint64_t bv = *(const uint64_t*)&Bbase[(ni * 8 + gr) * GP + kc];
                bf[ni][0] = (uint32_t)bv;
                bf[ni][1] = (uint32_t)(bv >> 32);
            }
#pragma unroll
            for (int mi = 0; mi < 4; mi++) {
                uint64_t aL = *(const uint64_t*)&Abase[(mi * 16 + gr) * GP + kc];
                uint64_t aH = *(const uint64_t*)&Abase[(mi * 16 + gr + 8) * GP + kc];
                const uint32_t a0 = (uint32_t)aL, a2 = (uint32_t)(aL >> 32);
                const uint32_t a1 = (uint32_t)aH, a3 = (uint32_t)(aH >> 32);
#pragma unroll
                for (int ni = 0; ni < 4; ni++)
                    mma_f16(acc[mi][ni], a0, a1, a2, a3, bf[ni][0], bf[ni][1]);
            }
        }
    }

    // ---------------- Register epilogue ----------------
#pragma unroll
    for (int mi = 0; mi < 4; mi++) {
#pragma unroll
        for (int half = 0; half < 2; half++) {
            const int m = m0 + wm * 64 + mi * 16 + gr + half * 8;
            const int bb = m >> 11;
            const int t = m & (T_SEQ - 1);
#pragma unroll
            for (int ni = 0; ni < 4; ni++) {
                const int n = n0 + wn * 32 + ni * 8 + tig * 2;
                float v0 = acc[mi][ni][half * 2 + 0] + bias[n];
                float v1 = acc[mi][ni][half * 2 + 1] + bias[n + 1];
                if (mode == 1 || mode == 2) {
                    const int hh = (n & 63) >> 1;
                    const float c = cosT[t * (HD / 2) + hh];
                    const float ss = sinT[t * (HD / 2) + hh];
                    const float e = v0 * c - v1 * ss;
                    const float o = v0 * ss + v1 * c;
                    v0 = e;
                    v1 = o;
                }
                if (mode == 0) {
                    *(float2*)&outC[(size_t)m * DMODEL + n] = make_float2(v0, v1);
                } else if (mode == 1) {
                    *(__half2*)&g_qh[(((size_t)(bb * NH + (n >> 6))) * T_SEQ + t) * HD + (n & 63)] =
                        __floats2half2_rn(v0 * QSCALE, v1 * QSCALE);
                } else {
                    const size_t idx =
                        (((size_t)(bb * NKV + (n >> 6))) * T_SEQ + t) * HD + (n & 63);
                    if (mode == 2) {
                        *(float2*)&kout[idx] = make_float2(v0, v1);
                        const int d = n & 63;
                        const int slot = ((d & 7) >> 1) * 4 + ((d >> 3) & 1) * 2;
                        const size_t base =
                            (((size_t)(bb * NKV + (n >> 6))) * T_SEQ + t) * HD +
                            (d & ~15) + slot;
                        *(__half2*)&g_kc[base] = __floats2half2_rn(v0, v1);
                    } else {
                        *(float2*)&vout[idx] = make_float2(v0, v1);
                    }
                }
            }
        }
    }
}

// ============================================================================
// Flash attention (R15 config) + ones-column-MMA row sum.
// 8 warps, warp tile 16x64, PERM16 K/V -> LDS.64 B-frags, pitch 80 halves,
// cp.async.ca double-buffered, heavy-first schedule, exp2-domain softmax.
// l accumulated by 4 extra HMMAs/iter (B = ones column: gr==0 ? 1h,1h : 0),
// replacing 16 FADD + 4 SHFL + 2 FMUL per thread-iter in the issue stream.
// ============================================================================
#define ATP 80
#define KVH (64 * ATP)

__global__ __launch_bounds__(256, 2) void attn_mma()
{
    extern __shared__ __align__(16) __half smh[];
    const uint32_t sm_addr = smem_u32(smh);

    const int tid = threadIdx.x;
    const int wid = tid >> 5;
    const int lane = tid & 31;
    const int gr = lane >> 2;
    const int tig = lane & 3;

    const int qt = (gridDim.x - 1) - blockIdx.x;  // heavy-first
    const int bh = blockIdx.y;
    const int b = bh >> 5;
    const int h = bh & 31;
    const int bkv = (b * NKV) + (h >> 2);

    const __half* Qg = g_qh + (((size_t)(b * NH + h)) * T_SEQ + qt * 128 + wid * 16) * HD;
    uint32_t qa[4][4];
#pragma unroll
    for (int j = 0; j < 4; j++) {
        const int d0 = 16 * j + 2 * tig;
        qa[j][0] = *(const uint32_t*)&Qg[gr * HD + d0];
        qa[j][1] = *(const uint32_t*)&Qg[(gr + 8) * HD + d0];
        qa[j][2] = *(const uint32_t*)&Qg[gr * HD + d0 + 8];
        qa[j][3] = *(const uint32_t*)&Qg[(gr + 8) * HD + d0 + 8];
    }

    const __half* Kbase = g_kc + (size_t)bkv * T_SEQ * HD;
    const __half* Vbase = g_vt + (size_t)bkv * HD * T_SEQ;

    float ctx[8][4];
#pragma unroll
    for (int ni = 0; ni < 8; ni++)
#pragma unroll
        for (int r = 0; r < 4; r++) ctx[ni][r] = 0.f;
    float lac[4] = {0.f, 0.f, 0.f, 0.f};          // l via ones-column MMA
    const uint32_t bones = (gr == 0) ? 0x3C003C00u : 0u;
    float mrun0 = -INFINITY, mrun1 = -INFINITY;

    const int lrow0 = tid >> 3;
    const int lch = tid & 7;
    const int row0 = qt * 128 + wid * 16 + gr;
    const int row1 = row0 + 8;
    const int njt = 2 * qt + 2;

#pragma unroll
    for (int i = 0; i < 2; i++) {
        const int r = lrow0 + i * 32;
        CP_ASYNC16_CA(sm_addr + (r * ATP + lch * 8) * 2, Kbase + (size_t)r * HD + lch * 8);
        CP_ASYNC16_CA(sm_addr + (2 * KVH + r * ATP + lch * 8) * 2,
                      Vbase + (size_t)r * T_SEQ + lch * 8);
    }
    CP_COMMIT();

    for (int jt = 0; jt < njt; jt++) {
        CP_WAIT0();
        __syncthreads();
        if (jt + 1 < njt) {
            const uint32_t boff = (uint32_t)((jt + 1) & 1) * KVH * 2;
            const int kt = (jt + 1) * 64;
#pragma unroll
            for (int i = 0; i < 2; i++) {
                const int r = lrow0 + i * 32;
                CP_ASYNC16_CA(sm_addr + boff + (r * ATP + lch * 8) * 2,
                              Kbase + (size_t)(kt + r) * HD + lch * 8);
                CP_ASYNC16_CA(sm_addr + 2 * KVH * 2 + boff + (r * ATP + lch * 8) * 2,
                              Vbase + (size_t)r * T_SEQ + kt + lch * 8);
            }
            CP_COMMIT();
        }

        if (jt == 2 * qt + 1 && wid < 4) continue;  // fully masked

        const __half* Ks = smh + (jt & 1) * KVH;
        const __half* Vt = smh + 2 * KVH + (jt & 1) * KVH;

        // ---- S (exp2 domain) = (Q*QSCALE) K^T ----
        float s[8][4];
#pragma unroll
        for (int ni = 0; ni < 8; ni++)
#pragma unroll
            for (int r = 0; r < 4; r++) s[ni][r] = 0.f;
#pragma unroll
        for (int j = 0; j < 4; j++) {
            const int kc = j * 16 + tig * 4;
#pragma unroll
            for (int ni = 0; ni < 8; ni++) {
                uint64_t bv = *(const uint64_t*)&Ks[(ni * 8 + gr) * ATP + kc];
                mma_f16(s[ni], qa[j][0], qa[j][1], qa[j][2], qa[j][3],
                        (uint32_t)bv, (uint32_t)(bv >> 32));
            }
        }

        // ---- causal mask ----
        if (jt >= 2 * qt) {
            const int colb = jt * 64 + 2 * tig;
#pragma unroll
            for (int ni = 0; ni < 8; ni++) {
                const int c0 = colb + 8 * ni;
                if (c0 > row0) s[ni][0] = -INFINITY;
                if (c0 + 1 > row0) s[ni][1] = -INFINITY;
                if (c0 > row1) s[ni][2] = -INFINITY;
                if (c0 + 1 > row1) s[ni][3] = -INFINITY;
            }
        }

        // ---- online softmax (exp2 domain; l via ones-MMA below) ----
        float m0 = -INFINITY, m1 = -INFINITY;
#pragma unroll
        for (int ni = 0; ni < 8; ni++) {
            m0 = fmaxf(m0, fmaxf(s[ni][0], s[ni][1]));
            m1 = fmaxf(m1, fmaxf(s[ni][2], s[ni][3]));
        }
        m0 = fmaxf(m0, __shfl_xor_sync(0xffffffffu, m0, 1, 4));
        m0 = fmaxf(m0, __shfl_xor_sync(0xffffffffu, m0, 2, 4));
        m1 = fmaxf(m1, __shfl_xor_sync(0xffffffffu, m1, 1, 4));
        m1 = fmaxf(m1, __shfl_xor_sync(0xffffffffu, m1, 2, 4));
        const float mn0 = fmaxf(mrun0, m0);
        const float mn1 = fmaxf(mrun1, m1);
        const float al0 = fast_exp2(mrun0 - mn0);
        const float al1 = fast_exp2(mrun1 - mn1);
#pragma unroll
        for (int ni = 0; ni < 8; ni++) {
            s[ni][0] = fast_exp2(s[ni][0] - mn0);
            s[ni][1] = fast_exp2(s[ni][1] - mn0);
            s[ni][2] = fast_exp2(s[ni][2] - mn1);
            s[ni][3] = fast_exp2(s[ni][3] - mn1);
            ctx[ni][0] *= al0;
            ctx[ni][1] *= al0;
            ctx[ni][2] *= al1;
            ctx[ni][3] *= al1;
        }
        lac[0] *= al0;
        lac[1] *= al0;
        lac[2] *= al1;
        lac[3] *= al1;
        mrun0 = mn0;
        mrun1 = mn1;

        // ---- ctx += P V (+ l += P * ones) ----
#pragma unroll
        for (int j = 0; j < 4; j++) {
            const uint32_t a0 = pack_h2(s[2 * j][0], s[2 * j][1]);
            const uint32_t a1 = pack_h2(s[2 * j][2], s[2 * j][3]);
            const uint32_t a2 = pack_h2(s[2 * j + 1][0], s[2 * j + 1][1]);
            const uint32_t a3 = pack_h2(s[2 * j + 1][2], s[2 * j + 1][3]);
            const int kc = j * 16 + tig * 4;
#pragma unroll
            for (int ni = 0; ni < 8; ni++) {
                uint64_t bv = *(const uint64_t*)&Vt[(ni * 8 + gr) * ATP + kc];
                mma_f16(ctx[ni], a0, a1, a2, a3, (uint32_t)bv, (uint32_t)(bv >> 32));
            }
            mma_f16(lac, a0, a1, a2, a3, bones, bones);
        }
    }

    // ---- finalize: l lives in col 0; broadcast within quad ----
    const float l0 = __shfl_sync(0xffffffffu, lac[0], 0, 4);
    const float l1 = __shfl_sync(0xffffffffu, lac[2], 0, 4);
    const float inv0 = 1.0f / l0;
    const float inv1 = 1.0f / l1;
    __half* o0 = g_ctx + (((size_t)(b * T_SEQ + row0)) * NH + h) * HD;
    __half* o1 = g_ctx + (((size_t)(b * T_SEQ + row1)) * NH + h) * HD;
#pragma unroll
    for (int ni = 0; ni < 8; ni++) {
        const int d = ni * 8 + 2 * tig;
        const int word = (d & ~15) + tig * 4 + (ni & 1) * 2;  // PERM slot
        *(__half2*)&o0[word] = __floats2half2_rn(ctx[ni][0] * inv0, ctx[ni][1] * inv0);
        *(__half2*)&o1[word] = __floats2half2_rn(ctx[ni][2] * inv1, ctx[ni][3] * inv1);
    }
}

// ---------------------------------------------------------------------------
extern "C" void kernel_launch(void* const* d_in, const int* in_sizes, int n_in,
                              void* d_out, int out_size)
{
    const float* x    = (const float*)d_in[0];
    const float* cosT = (const float*)d_in[1];
    const float* sinT = (const float*)d_in[2];
    const float* wq   = (const float*)d_in[3];
    const float* bq   = (const float*)d_in[4];
    const float* wk   = (const float*)d_in[5];
    const float* bk   = (const float*)d_in[6];
    const float* wv   = (const float*)d_in[7];
    const float* bv   = (const float*)d_in[8];
    const float* wo   = (const float*)d_in[9];
    const float* bo   = (const float*)d_in[10];

    float* out  = (float*)d_out;            // (B, T, D)
    float* kout = out + (size_t)8388608;    // (B, KV, T, HD)
    float* vout = out + (size_t)10485760;   // (B, KV, T, HD)

    const int GEMM_SMEM = 4 * TILE_H * 2;   // 81920 B
    const int ATTN_SMEM = 4 * KVH * 2;      // 40960 B
    static bool attr_set = false;
    if (!attr_set) {
        cudaFuncSetAttribute(db_gemm<0>, cudaFuncAttributeMaxDynamicSharedMemorySize, GEMM_SMEM);
        cudaFuncSetAttribute(db_gemm<1>, cudaFuncAttributeMaxDynamicSharedMemorySize, GEMM_SMEM);
        cudaFuncSetAttribute(attn_mma, cudaFuncAttributeMaxDynamicSharedMemorySize, ATTN_SMEM);
        attr_set = true;
    }

    __half* p_xt;  cudaGetSymbolAddress((void**)&p_xt, g_xt);
    __half* p_wq;  cudaGetSymbolAddress((void**)&p_wq, g_wq);
    __half* p_wk;  cudaGetSymbolAddress((void**)&p_wk, g_wk);
    __half* p_wv;  cudaGetSymbolAddress((void**)&p_wv, g_wv);
    __half* p_wo;  cudaGetSymbolAddress((void**)&p_wo, g_wo);
    __half* p_vt;  cudaGetSymbolAddress((void**)&p_vt, g_vt);

    // Prep: fp32 -> fp16 PERM16, one launch
    cvt_all<<<18432, 256>>>(x, wq, wk, wv, wo, p_xt, p_wq, p_wk, p_wv, p_wo);

    // Fused QKV projections (+RoPE; Q -> fp16*QSCALE, K -> fp32 + fp16 PERM16)
    db_gemm<0><<<dim3(24, 32), 256, GEMM_SMEM>>>(
        p_xt, bq, bk, bv, kout, vout, nullptr, cosT, sinT);

    // V -> transposed PERM16 fp16
    vtrans<<<dim3(32, 16), 256>>>(vout, p_vt);

    // Attention -> g_ctx (PERM16 fp16)
    attn_mma<<<dim3(T_SEQ / 128, 2 * NH), 256, ATTN_SMEM>>>();

    // Output projection -> out
    db_gemm<1><<<dim3(16, 32), 256, GEMM_SMEM>>>(
        nullptr, bo, nullptr, nullptr, nullptr, nullptr, out, nullptr, nullptr);
}